// round 4
// baseline (speedup 1.0000x reference)
#include <cuda_runtime.h>
#include <stdint.h>

#define NPTS   262144
#define GRIDE  256
#define TSIZE  (256*256*256)
#define NK     26
#define BM     128
#define NTILES (NPTS / BM)   // 2048
#define CGRID  296           // persistent center grid (2 CTAs/SM target)
#define PMAXT  40

typedef unsigned long long ull;

// ---------------- scratch ---------------------------------------------------
__device__ int  g_table[TSIZE];        // idx+1, 0 = empty
__device__ int  g_counts[NK];
__device__ int2 g_pairs[NK * NPTS];

// ---------------- f32x2 helpers ---------------------------------------------
__device__ __forceinline__ ull ffma2(ull a, ull b, ull c) {
    ull d;
    asm("fma.rn.f32x2 %0, %1, %2, %3;" : "=l"(d) : "l"(a), "l"(b), "l"(c));
    return d;
}
__device__ __forceinline__ ull pack2(float lo, float hi) {
    ull r;
    asm("mov.b64 %0, {%1, %2};" : "=l"(r) : "f"(lo), "f"(hi));
    return r;
}
__device__ __forceinline__ void unpack2(ull v, float& lo, float& hi) {
    asm("mov.b64 {%0, %1}, %2;" : "=f"(lo), "=f"(hi) : "l"(v));
}
__device__ __forceinline__ void red4(float* p, float a, float b, float c, float d) {
    asm volatile("red.global.add.v4.f32 [%0], {%1,%2,%3,%4};"
                 :: "l"(p), "f"(a), "f"(b), "f"(c), "f"(d) : "memory");
}

// ---------------- smem layout (bytes) ---------------------------------------
// WS2: [64 ci][8 n-chunks][10 ull] (8 dup-W couts + 2 pad) = 40960
//      tx stride 80B -> banks {0,20,8,28,16,4,24,12}: conflict-free
// FS : [64 ci][32 m-chunks][8 f32] (4 feats + 4 pad) = 65536 (row 1024B)
//      ty stride 32B -> per-warp banks {0,8,16,24}: conflict-free, 16B-aligned
#define SM_WS2  0
#define SM_FS   40960
#define SM_JJ   106496
#define SM_II   107008
#define SM_TOT  107520

// ---------------- 1) clear ---------------------------------------------------
__global__ __launch_bounds__(256) void k_clear(const int* __restrict__ coords) {
    int i = blockIdx.x * 256 + threadIdx.x;
    if (blockIdx.x == 0 && threadIdx.x < NK) g_counts[threadIdx.x] = 0;
    int x = coords[3*i], y = coords[3*i+1], z = coords[3*i+2];
    g_table[(x * GRIDE + y) * GRIDE + z] = 0;
}

// ---------------- 2) insert --------------------------------------------------
__global__ __launch_bounds__(256) void k_insert(const int* __restrict__ coords) {
    int i = blockIdx.x * 256 + threadIdx.x;
    int x = coords[3*i], y = coords[3*i+1], z = coords[3*i+2];
    atomicMax(&g_table[(x * GRIDE + y) * GRIDE + z], i + 1);
}

// ---------------- 3) probe ---------------------------------------------------
__global__ __launch_bounds__(256) void k_probe(const int* __restrict__ coords) {
    int i = blockIdx.x * 256 + threadIdx.x;
    int x = coords[3*i], y = coords[3*i+1], z = coords[3*i+2];
    int lane = threadIdx.x & 31;
    int j[NK];
    #pragma unroll
    for (int kk = 0; kk < NK; kk++) {
        int k  = kk + (kk >= 13);
        int nx = x + k / 9 - 1;
        int ny = y + (k / 3) % 3 - 1;
        int nz = z + k % 3 - 1;
        bool inb = ((unsigned)nx < 256u) && ((unsigned)ny < 256u) && ((unsigned)nz < 256u);
        j[kk] = inb ? g_table[(nx * GRIDE + ny) * GRIDE + nz] : 0;
    }
    #pragma unroll
    for (int kk = 0; kk < NK; kk++) {
        bool valid = j[kk] > 0;
        unsigned m = __ballot_sync(0xffffffffu, valid);
        if (!m) continue;
        int leader = __ffs(m) - 1;
        int pos = 0;
        if (lane == leader) pos = atomicAdd(&g_counts[kk], __popc(m));
        pos = __shfl_sync(0xffffffffu, pos, leader);
        if (valid) {
            int mypos = pos + __popc(m & ((1u << lane) - 1u));
            g_pairs[kk * NPTS + mypos] = make_int2(i, j[kk] - 1);
        }
    }
}

// ---------------- shared GEMM pieces ----------------------------------------
__device__ __forceinline__ void load_w_dup(ull* WS2, const float* __restrict__ Wk, int tid) {
    #pragma unroll 4
    for (int e = tid; e < 4096; e += 256) {
        float w = Wk[e];
        int ci = e >> 6, co = e & 63;
        WS2[ci * 80 + (co >> 3) * 10 + (co & 7)] = pack2(w, w);
    }
}

__device__ __forceinline__ void gather_fs(float* FS, const int* JJ,
                                          const float* __restrict__ feats, int tid) {
    #pragma unroll
    for (int it = 0; it < 8; it++) {
        int idx = tid + it * 256;
        int m  = idx & 127;
        int cq = idx >> 7;                        // 0..15
        float4 v = *(const float4*)(feats + (size_t)JJ[m] * 64 + cq * 4);
        int mb = (m >> 2) * 8 + (m & 3);          // float index within row
        float* f = FS + (cq * 4) * 256 + mb;      // row = 256 floats (1024B)
        f[0]   = v.x;
        f[256] = v.y;
        f[512] = v.z;
        f[768] = v.w;
    }
}

// compute acc[2][8]: 2 m-pairs (f32x2) x 8 couts
__device__ __forceinline__ void gemm_core(ull acc[2][8], const float* FS,
                                          const ull* WS2, int tx, int ty) {
    #pragma unroll 8
    for (int ci = 0; ci < 64; ci++) {
        ulonglong2 a = *(const ulonglong2*)(FS + ci * 256 + ty * 8);
        const ulonglong2* wq = (const ulonglong2*)(WS2 + ci * 80 + tx * 10);
        ulonglong2 w0 = wq[0], w1 = wq[1], w2 = wq[2], w3 = wq[3];
        ull wp[8] = {w0.x, w0.y, w1.x, w1.y, w2.x, w2.y, w3.x, w3.y};
        #pragma unroll
        for (int n = 0; n < 8; n++) {
            acc[0][n] = ffma2(a.x, wp[n], acc[0][n]);
            acc[1][n] = ffma2(a.y, wp[n], acc[1][n]);
        }
    }
}

// ---------------- 4) center tap: persistent gathered GEMM -------------------
__global__ __launch_bounds__(256, 2) void k_center(const int* __restrict__ coords,
                                                   const float* __restrict__ feats,
                                                   const float* __restrict__ kw,
                                                   float* __restrict__ out) {
    extern __shared__ unsigned char sm[];
    ull*   WS2 = (ull*)(sm + SM_WS2);
    float* FS  = (float*)(sm + SM_FS);
    int*   JJ  = (int*)(sm + SM_JJ);

    int tid = threadIdx.x;
    int tx = tid & 7, ty = tid >> 3;              // tx: 8 n-chunks, ty: 32 m-chunks(4m)

    load_w_dup(WS2, kw + 13 * 4096, tid);

    for (int t = blockIdx.x; t < NTILES; t += CGRID) {
        int base = t * BM;
        __syncthreads();                          // FS/JJ safe to overwrite
        if (tid < BM) {
            int i = base + tid;
            int lin = (coords[3*i] * GRIDE + coords[3*i+1]) * GRIDE + coords[3*i+2];
            JJ[tid] = g_table[lin] - 1;           // always occupied (self)
        }
        __syncthreads();
        gather_fs(FS, JJ, feats, tid);
        __syncthreads();

        ull acc[2][8];
        #pragma unroll
        for (int p = 0; p < 2; p++)
            #pragma unroll
            for (int n = 0; n < 8; n++) acc[p][n] = 0ULL;

        gemm_core(acc, FS, WS2, tx, ty);

        #pragma unroll
        for (int p = 0; p < 2; p++) {
            float lo[8], hi[8];
            #pragma unroll
            for (int n = 0; n < 8; n++) unpack2(acc[p][n], lo[n], hi[n]);
            int i0 = base + ty * 4 + 2 * p;
            float* o0 = out + (size_t)i0 * 64 + tx * 8;
            *(float4*)(o0)     = make_float4(lo[0], lo[1], lo[2], lo[3]);
            *(float4*)(o0 + 4) = make_float4(lo[4], lo[5], lo[6], lo[7]);
            float* o1 = o0 + 64;
            *(float4*)(o1)     = make_float4(hi[0], hi[1], hi[2], hi[3]);
            *(float4*)(o1 + 4) = make_float4(hi[4], hi[5], hi[6], hi[7]);
        }
    }
}

// ---------------- 5) off-center taps: tiled GEMM + red.v4 scatter -----------
__global__ __launch_bounds__(256, 2) void k_pairs(const float* __restrict__ feats,
                                                  const float* __restrict__ kw,
                                                  float* __restrict__ out) {
    int kk  = blockIdx.x;
    int cnt = g_counts[kk];
    if ((int)(blockIdx.y * BM) >= cnt) return;    // CTA-uniform early exit
    int k   = kk + (kk >= 13);
    int tid = threadIdx.x;

    extern __shared__ unsigned char sm[];
    ull*   WS2 = (ull*)(sm + SM_WS2);
    float* FS  = (float*)(sm + SM_FS);
    int*   JJ  = (int*)(sm + SM_JJ);
    int*   II  = (int*)(sm + SM_II);

    load_w_dup(WS2, kw + k * 4096, tid);

    int tx = tid & 7, ty = tid >> 3;

    for (int t = blockIdx.y; t * BM < cnt; t += PMAXT) {
        int tb = t * BM;
        __syncthreads();
        if (tid < BM) {
            int p = tb + tid;
            if (p < cnt) {
                int2 pr = g_pairs[kk * NPTS + p];
                JJ[tid] = pr.y;
                II[tid] = pr.x;
            } else {
                JJ[tid] = 0;
                II[tid] = -1;
            }
        }
        __syncthreads();
        gather_fs(FS, JJ, feats, tid);
        __syncthreads();

        ull acc[2][8];
        #pragma unroll
        for (int p = 0; p < 2; p++)
            #pragma unroll
            for (int n = 0; n < 8; n++) acc[p][n] = 0ULL;

        gemm_core(acc, FS, WS2, tx, ty);

        #pragma unroll
        for (int p = 0; p < 2; p++) {
            float lo[8], hi[8];
            #pragma unroll
            for (int n = 0; n < 8; n++) unpack2(acc[p][n], lo[n], hi[n]);
            int m0 = ty * 4 + 2 * p;
            int i0 = II[m0];
            if (i0 >= 0) {
                float* o = out + (size_t)i0 * 64 + tx * 8;
                red4(o,     lo[0], lo[1], lo[2], lo[3]);
                red4(o + 4, lo[4], lo[5], lo[6], lo[7]);
            }
            int i1 = II[m0 + 1];
            if (i1 >= 0) {
                float* o = out + (size_t)i1 * 64 + tx * 8;
                red4(o,     hi[0], hi[1], hi[2], hi[3]);
                red4(o + 4, hi[4], hi[5], hi[6], hi[7]);
            }
        }
    }
}

// ---------------- launch -----------------------------------------------------
extern "C" void kernel_launch(void* const* d_in, const int* in_sizes, int n_in,
                              void* d_out, int out_size) {
    const int*   coords = (const int*)d_in[0];
    const float* feats  = (const float*)d_in[1];
    const float* kw     = (const float*)d_in[2];
    float*       out    = (float*)d_out;

    cudaFuncSetAttribute(k_center, cudaFuncAttributeMaxDynamicSharedMemorySize, SM_TOT);
    cudaFuncSetAttribute(k_pairs,  cudaFuncAttributeMaxDynamicSharedMemorySize, SM_TOT);

    k_clear <<<NPTS / 256, 256>>>(coords);
    k_insert<<<NPTS / 256, 256>>>(coords);
    k_probe <<<NPTS / 256, 256>>>(coords);
    k_center<<<CGRID, 256, SM_TOT>>>(coords, feats, kw, out);
    k_pairs <<<dim3(NK, PMAXT), 256, SM_TOT>>>(feats, kw, out);
}

// round 5
// speedup vs baseline: 1.1241x; 1.1241x over previous
#include <cuda_runtime.h>
#include <stdint.h>

#define NPTS   262144
#define GRIDE  256
#define TSIZE  (256*256*256)
#define NK     26
#define BM     128
#define NTILES (NPTS / BM)   // 2048
#define CGRID  444           // persistent center grid (3 CTAs/SM)
#define PMAXT  40

typedef unsigned long long ull;

// ---------------- scratch ---------------------------------------------------
__device__ int  g_table[TSIZE];        // idx+1, 0 = empty
__device__ int  g_counts[NK];
__device__ int2 g_pairs[NK * NPTS];

// ---------------- f32x2 helpers ---------------------------------------------
__device__ __forceinline__ ull ffma2(ull a, ull b, ull c) {
    ull d;
    asm("fma.rn.f32x2 %0, %1, %2, %3;" : "=l"(d) : "l"(a), "l"(b), "l"(c));
    return d;
}
__device__ __forceinline__ ull pack2(float lo, float hi) {
    ull r;
    asm("mov.b64 %0, {%1, %2};" : "=l"(r) : "f"(lo), "f"(hi));
    return r;
}
__device__ __forceinline__ void unpack2(ull v, float& lo, float& hi) {
    asm("mov.b64 {%0, %1}, %2;" : "=f"(lo), "=f"(hi) : "l"(v));
}
__device__ __forceinline__ void red4(float* p, float a, float b, float c, float d) {
    asm volatile("red.global.add.v4.f32 [%0], {%1,%2,%3,%4};"
                 :: "l"(p), "f"(a), "f"(b), "f"(c), "f"(d) : "memory");
}

// ---------------- smem layout (bytes) ---------------------------------------
// WS2: [64 ci][8 warp-n-chunks][8 ull dup-W] = 32768   (warp-broadcast reads)
// FS : [64 ci][128 f32 m]                    = 32768   (contiguous 512B rows)
#define SM_WS2  0
#define SM_FS   32768
#define SM_JJ   65536
#define SM_II   66048
#define SM_TOT  66560

// ---------------- 1) clear ---------------------------------------------------
__global__ __launch_bounds__(256) void k_clear(const int* __restrict__ coords) {
    int i = blockIdx.x * 256 + threadIdx.x;
    if (blockIdx.x == 0 && threadIdx.x < NK) g_counts[threadIdx.x] = 0;
    int x = coords[3*i], y = coords[3*i+1], z = coords[3*i+2];
    g_table[(x * GRIDE + y) * GRIDE + z] = 0;
}

// ---------------- 2) insert --------------------------------------------------
__global__ __launch_bounds__(256) void k_insert(const int* __restrict__ coords) {
    int i = blockIdx.x * 256 + threadIdx.x;
    int x = coords[3*i], y = coords[3*i+1], z = coords[3*i+2];
    atomicMax(&g_table[(x * GRIDE + y) * GRIDE + z], i + 1);
}

// ---------------- 3) probe ---------------------------------------------------
__global__ __launch_bounds__(256) void k_probe(const int* __restrict__ coords) {
    int i = blockIdx.x * 256 + threadIdx.x;
    int x = coords[3*i], y = coords[3*i+1], z = coords[3*i+2];
    int lane = threadIdx.x & 31;
    int j[NK];
    #pragma unroll
    for (int kk = 0; kk < NK; kk++) {
        int k  = kk + (kk >= 13);
        int nx = x + k / 9 - 1;
        int ny = y + (k / 3) % 3 - 1;
        int nz = z + k % 3 - 1;
        bool inb = ((unsigned)nx < 256u) && ((unsigned)ny < 256u) && ((unsigned)nz < 256u);
        j[kk] = inb ? g_table[(nx * GRIDE + ny) * GRIDE + nz] : 0;
    }
    #pragma unroll
    for (int kk = 0; kk < NK; kk++) {
        bool valid = j[kk] > 0;
        unsigned m = __ballot_sync(0xffffffffu, valid);
        if (!m) continue;
        int leader = __ffs(m) - 1;
        int pos = 0;
        if (lane == leader) pos = atomicAdd(&g_counts[kk], __popc(m));
        pos = __shfl_sync(0xffffffffu, pos, leader);
        if (valid) {
            int mypos = pos + __popc(m & ((1u << lane) - 1u));
            g_pairs[kk * NPTS + mypos] = make_int2(i, j[kk] - 1);
        }
    }
}

// ---------------- shared GEMM pieces ----------------------------------------
// WS2[ci*64 + (co>>3)*8 + (co&7)] = dup(w)
__device__ __forceinline__ void load_w_dup(ull* WS2, const float* __restrict__ Wk, int tid) {
    #pragma unroll 4
    for (int e = tid; e < 4096; e += 256) {
        float w = Wk[e];
        int ci = e >> 6, co = e & 63;
        WS2[ci * 64 + co] = pack2(w, w);   // co = (chunk<<3)|idx, already matches
    }
}

// FS[ci*128 + m]
__device__ __forceinline__ void gather_fs(float* FS, const int* JJ,
                                          const float* __restrict__ feats, int tid) {
    #pragma unroll
    for (int it = 0; it < 8; it++) {
        int idx = tid + it * 256;
        int m  = idx & 127;
        int cq = idx >> 7;                        // 0..15
        float4 v = *(const float4*)(feats + (size_t)JJ[m] * 64 + cq * 4);
        float* f = FS + (cq * 4) * 128 + m;
        f[0]   = v.x;
        f[128] = v.y;
        f[256] = v.z;
        f[384] = v.w;
    }
}

// acc[2][8]: lane's 2 m-pairs x warp's 8 couts.  W reads are warp-broadcast.
__device__ __forceinline__ void gemm_core(ull acc[2][8], const float* FS,
                                          const ull* WS2, int wid, int lane) {
    const float* fa = FS + lane * 4;
    const ull*   wb = WS2 + wid * 8;
    #pragma unroll 8
    for (int ci = 0; ci < 64; ci++) {
        ulonglong2 a = *(const ulonglong2*)(fa + ci * 128);
        const ulonglong2* wq = (const ulonglong2*)(wb + ci * 64);
        ulonglong2 w0 = wq[0], w1 = wq[1], w2 = wq[2], w3 = wq[3];
        ull wp[8] = {w0.x, w0.y, w1.x, w1.y, w2.x, w2.y, w3.x, w3.y};
        #pragma unroll
        for (int n = 0; n < 8; n++) {
            acc[0][n] = ffma2(a.x, wp[n], acc[0][n]);
            acc[1][n] = ffma2(a.y, wp[n], acc[1][n]);
        }
    }
}

// ---------------- 4) center tap: persistent gathered GEMM -------------------
__global__ __launch_bounds__(256, 3) void k_center(const int* __restrict__ coords,
                                                   const float* __restrict__ feats,
                                                   const float* __restrict__ kw,
                                                   float* __restrict__ out) {
    extern __shared__ unsigned char sm[];
    ull*   WS2 = (ull*)(sm + SM_WS2);
    float* FS  = (float*)(sm + SM_FS);
    int*   JJ  = (int*)(sm + SM_JJ);

    int tid = threadIdx.x, wid = tid >> 5, lane = tid & 31;

    load_w_dup(WS2, kw + 13 * 4096, tid);

    for (int t = blockIdx.x; t < NTILES; t += CGRID) {
        int base = t * BM;
        __syncthreads();                          // FS/JJ safe to overwrite
        if (tid < BM) {
            int i = base + tid;
            int lin = (coords[3*i] * GRIDE + coords[3*i+1]) * GRIDE + coords[3*i+2];
            JJ[tid] = g_table[lin] - 1;           // always occupied (self)
        }
        __syncthreads();
        gather_fs(FS, JJ, feats, tid);
        __syncthreads();

        ull acc[2][8];
        #pragma unroll
        for (int p = 0; p < 2; p++)
            #pragma unroll
            for (int n = 0; n < 8; n++) acc[p][n] = 0ULL;

        gemm_core(acc, FS, WS2, wid, lane);

        #pragma unroll
        for (int p = 0; p < 2; p++) {
            float lo[8], hi[8];
            #pragma unroll
            for (int n = 0; n < 8; n++) unpack2(acc[p][n], lo[n], hi[n]);
            int i0 = base + lane * 4 + 2 * p;
            float* o0 = out + (size_t)i0 * 64 + wid * 8;
            *(float4*)(o0)     = make_float4(lo[0], lo[1], lo[2], lo[3]);
            *(float4*)(o0 + 4) = make_float4(lo[4], lo[5], lo[6], lo[7]);
            float* o1 = o0 + 64;
            *(float4*)(o1)     = make_float4(hi[0], hi[1], hi[2], hi[3]);
            *(float4*)(o1 + 4) = make_float4(hi[4], hi[5], hi[6], hi[7]);
        }
    }
}

// ---------------- 5) off-center taps: tiled GEMM + red.v4 scatter -----------
__global__ __launch_bounds__(256, 3) void k_pairs(const float* __restrict__ feats,
                                                  const float* __restrict__ kw,
                                                  float* __restrict__ out) {
    int kk  = blockIdx.x;
    int cnt = g_counts[kk];
    if ((int)(blockIdx.y * BM) >= cnt) return;    // CTA-uniform early exit
    int k   = kk + (kk >= 13);
    int tid = threadIdx.x, wid = tid >> 5, lane = tid & 31;

    extern __shared__ unsigned char sm[];
    ull*   WS2 = (ull*)(sm + SM_WS2);
    float* FS  = (float*)(sm + SM_FS);
    int*   JJ  = (int*)(sm + SM_JJ);
    int*   II  = (int*)(sm + SM_II);

    load_w_dup(WS2, kw + k * 4096, tid);

    for (int t = blockIdx.y; t * BM < cnt; t += PMAXT) {
        int tb = t * BM;
        __syncthreads();
        if (tid < BM) {
            int p = tb + tid;
            if (p < cnt) {
                int2 pr = g_pairs[kk * NPTS + p];
                JJ[tid] = pr.y;
                II[tid] = pr.x;
            } else {
                JJ[tid] = 0;
                II[tid] = -1;
            }
        }
        __syncthreads();
        gather_fs(FS, JJ, feats, tid);
        __syncthreads();

        ull acc[2][8];
        #pragma unroll
        for (int p = 0; p < 2; p++)
            #pragma unroll
            for (int n = 0; n < 8; n++) acc[p][n] = 0ULL;

        gemm_core(acc, FS, WS2, wid, lane);

        #pragma unroll
        for (int p = 0; p < 2; p++) {
            float lo[8], hi[8];
            #pragma unroll
            for (int n = 0; n < 8; n++) unpack2(acc[p][n], lo[n], hi[n]);
            int m0 = lane * 4 + 2 * p;
            int i0 = II[m0];
            if (i0 >= 0) {
                float* o = out + (size_t)i0 * 64 + wid * 8;
                red4(o,     lo[0], lo[1], lo[2], lo[3]);
                red4(o + 4, lo[4], lo[5], lo[6], lo[7]);
            }
            int i1 = II[m0 + 1];
            if (i1 >= 0) {
                float* o = out + (size_t)i1 * 64 + wid * 8;
                red4(o,     hi[0], hi[1], hi[2], hi[3]);
                red4(o + 4, hi[4], hi[5], hi[6], hi[7]);
            }
        }
    }
}

// ---------------- launch -----------------------------------------------------
extern "C" void kernel_launch(void* const* d_in, const int* in_sizes, int n_in,
                              void* d_out, int out_size) {
    const int*   coords = (const int*)d_in[0];
    const float* feats  = (const float*)d_in[1];
    const float* kw     = (const float*)d_in[2];
    float*       out    = (float*)d_out;

    cudaFuncSetAttribute(k_center, cudaFuncAttributeMaxDynamicSharedMemorySize, SM_TOT);
    cudaFuncSetAttribute(k_pairs,  cudaFuncAttributeMaxDynamicSharedMemorySize, SM_TOT);

    k_clear <<<NPTS / 256, 256>>>(coords);
    k_insert<<<NPTS / 256, 256>>>(coords);
    k_probe <<<NPTS / 256, 256>>>(coords);
    k_center<<<CGRID, 256, SM_TOT>>>(coords, feats, kw, out);
    k_pairs <<<dim3(NK, PMAXT), 256, SM_TOT>>>(feats, kw, out);
}

// round 6
// speedup vs baseline: 1.1752x; 1.0455x over previous
#include <cuda_runtime.h>
#include <stdint.h>

#define NPTS   262144
#define GRIDE  256
#define TSIZE  (256*256*256)
#define NK     26
#define BM     256          // gemm tile (points/pairs)
#define NTILES (NPTS / BM)  // 1024
#define CGRID  296          // persistent center grid (2 CTAs/SM)
#define PMAXT  16
#define FSS    260          // FS row stride in floats (256 + 4 pad)

typedef unsigned long long ull;

// ---------------- scratch ---------------------------------------------------
__device__ int  g_table[TSIZE];        // idx+1, 0 = empty
__device__ int  g_counts[NK];
__device__ int2 g_pairs[NK * NPTS];

// ---------------- f32x2 helpers ---------------------------------------------
__device__ __forceinline__ ull ffma2(ull a, ull b, ull c) {
    ull d;
    asm("fma.rn.f32x2 %0, %1, %2, %3;" : "=l"(d) : "l"(a), "l"(b), "l"(c));
    return d;
}
__device__ __forceinline__ ull pack2(float lo, float hi) {
    ull r;
    asm("mov.b64 %0, {%1, %2};" : "=l"(r) : "f"(lo), "f"(hi));
    return r;
}
__device__ __forceinline__ void unpack2(ull v, float& lo, float& hi) {
    asm("mov.b64 {%0, %1}, %2;" : "=f"(lo), "=f"(hi) : "l"(v));
}
__device__ __forceinline__ ull swap2(ull v) {
    float lo, hi;
    unpack2(v, lo, hi);
    return pack2(hi, lo);
}
__device__ __forceinline__ void red4(float* p, float a, float b, float c, float d) {
    asm volatile("red.global.add.v4.f32 [%0], {%1,%2,%3,%4};"
                 :: "l"(p), "f"(a), "f"(b), "f"(c), "f"(d) : "memory");
}

// ---------------- smem layout (bytes) ---------------------------------------
// WP : [64 ci][32 co-pairs (ull)] natural f32x2 pairs   = 16384
// FS : [64 ci][FSS floats], position = m ^ (ci & 60)    = 66560
#define SM_WP   0
#define SM_FS   16384
#define SM_JJ   82944
#define SM_II   83968
#define SM_TOT  84992

// ---------------- 1) clear ---------------------------------------------------
__global__ __launch_bounds__(256) void k_clear(const int* __restrict__ coords) {
    int i = blockIdx.x * 256 + threadIdx.x;
    if (blockIdx.x == 0 && threadIdx.x < NK) g_counts[threadIdx.x] = 0;
    int x = coords[3*i], y = coords[3*i+1], z = coords[3*i+2];
    g_table[(x * GRIDE + y) * GRIDE + z] = 0;
}

// ---------------- 2) insert --------------------------------------------------
__global__ __launch_bounds__(256) void k_insert(const int* __restrict__ coords) {
    int i = blockIdx.x * 256 + threadIdx.x;
    int x = coords[3*i], y = coords[3*i+1], z = coords[3*i+2];
    atomicMax(&g_table[(x * GRIDE + y) * GRIDE + z], i + 1);
}

// ---------------- 3) probe ---------------------------------------------------
__global__ __launch_bounds__(256) void k_probe(const int* __restrict__ coords) {
    int i = blockIdx.x * 256 + threadIdx.x;
    int x = coords[3*i], y = coords[3*i+1], z = coords[3*i+2];
    int lane = threadIdx.x & 31;
    int j[NK];
    #pragma unroll
    for (int kk = 0; kk < NK; kk++) {
        int k  = kk + (kk >= 13);
        int nx = x + k / 9 - 1;
        int ny = y + (k / 3) % 3 - 1;
        int nz = z + k % 3 - 1;
        bool inb = ((unsigned)nx < 256u) && ((unsigned)ny < 256u) && ((unsigned)nz < 256u);
        j[kk] = inb ? g_table[(nx * GRIDE + ny) * GRIDE + nz] : 0;
    }
    #pragma unroll
    for (int kk = 0; kk < NK; kk++) {
        bool valid = j[kk] > 0;
        unsigned m = __ballot_sync(0xffffffffu, valid);
        if (!m) continue;
        int leader = __ffs(m) - 1;
        int pos = 0;
        if (lane == leader) pos = atomicAdd(&g_counts[kk], __popc(m));
        pos = __shfl_sync(0xffffffffu, pos, leader);
        if (valid) {
            int mypos = pos + __popc(m & ((1u << lane) - 1u));
            g_pairs[kk * NPTS + mypos] = make_int2(i, j[kk] - 1);
        }
    }
}

// ---------------- shared GEMM pieces ----------------------------------------
// WP[ci*32 + p] = (w[ci][2p], w[ci][2p+1]) as f32x2
__device__ __forceinline__ void load_w(ull* WP, const float* __restrict__ Wk, int tid) {
    #pragma unroll 4
    for (int e = tid; e < 2048; e += 256) {
        int ci = e >> 5, p = e & 31;
        float2 w = *(const float2*)(Wk + ci * 64 + 2 * p);
        WP[ci * 32 + p] = pack2(w.x, w.y);
    }
}

// coalesced gather: 16 lanes per row (one float4 each), swizzled STS (2-way)
__device__ __forceinline__ void gather_fs(float* FS, const int* JJ,
                                          const float* __restrict__ feats, int tid) {
    #pragma unroll
    for (int it = 0; it < 16; it++) {
        int idx = it * 256 + tid;
        int m = idx >> 4, s = idx & 15;
        float4 v = *(const float4*)(feats + (size_t)JJ[m] * 64 + s * 4);
        int pos = m ^ (s * 4);                  // xor value = ci&60 = 4s
        float* f = FS + (s * 4) * FSS + pos;
        f[0]       = v.x;
        f[FSS]     = v.y;
        f[2 * FSS] = v.z;
        f[3 * FSS] = v.w;
    }
}

// lane: 4 m (2 f32x2 pairs) x 16 co (8 pairs); diag + antidiag accumulators
__device__ __forceinline__ void gemm_core(ull accd[2][8], ull accx[2][8],
                                          const float* FS, const ull* WP,
                                          int cw, int h, int lane) {
    const float* fbase = FS + h * 128;
    const ull*   wbase = WP + cw * 8;
    #pragma unroll 4
    for (int ci = 0; ci < 64; ci++) {
        int xorv = ci & 60;
        ulonglong2 av = *(const ulonglong2*)(fbase + ci * FSS + ((lane * 4) ^ xorv));
        ull a0 = av.x, a1 = av.y;
        ull a0s = swap2(a0), a1s = swap2(a1);
        const ulonglong2* wq = (const ulonglong2*)(wbase + ci * 32);
        ulonglong2 w0 = wq[0], w1 = wq[1], w2 = wq[2], w3 = wq[3];
        ull wp[8] = {w0.x, w0.y, w1.x, w1.y, w2.x, w2.y, w3.x, w3.y};
        #pragma unroll
        for (int n = 0; n < 8; n++) {
            accd[0][n] = ffma2(a0,  wp[n], accd[0][n]);
            accx[0][n] = ffma2(a0s, wp[n], accx[0][n]);
            accd[1][n] = ffma2(a1,  wp[n], accd[1][n]);
            accx[1][n] = ffma2(a1s, wp[n], accx[1][n]);
        }
    }
}

// ---------------- 4) center tap: persistent gathered GEMM -------------------
__global__ __launch_bounds__(256, 2) void k_center(const int* __restrict__ coords,
                                                   const float* __restrict__ feats,
                                                   const float* __restrict__ kw,
                                                   float* __restrict__ out) {
    extern __shared__ unsigned char sm[];
    ull*   WP = (ull*)(sm + SM_WP);
    float* FS = (float*)(sm + SM_FS);
    int*   JJ = (int*)(sm + SM_JJ);

    int tid = threadIdx.x, wid = tid >> 5, lane = tid & 31;
    int cw = wid >> 1, h = wid & 1;             // co-chunk (16 co), m-half (128 m)

    load_w(WP, kw + 13 * 4096, tid);

    for (int t = blockIdx.x; t < NTILES; t += CGRID) {
        int base = t * BM;
        __syncthreads();                        // FS/JJ safe to overwrite
        {
            int i = base + tid;
            int lin = (coords[3*i] * GRIDE + coords[3*i+1]) * GRIDE + coords[3*i+2];
            JJ[tid] = g_table[lin] - 1;         // always occupied (self)
        }
        __syncthreads();
        gather_fs(FS, JJ, feats, tid);
        __syncthreads();

        ull accd[2][8], accx[2][8];
        #pragma unroll
        for (int p = 0; p < 2; p++)
            #pragma unroll
            for (int n = 0; n < 8; n++) { accd[p][n] = 0ULL; accx[p][n] = 0ULL; }

        gemm_core(accd, accx, FS, WP, cw, h, lane);

        #pragma unroll
        for (int p = 0; p < 2; p++) {
            float dlo[8], dhi[8], xlo[8], xhi[8];
            #pragma unroll
            for (int n = 0; n < 8; n++) {
                unpack2(accd[p][n], dlo[n], dhi[n]);
                unpack2(accx[p][n], xlo[n], xhi[n]);
            }
            int m0 = base + h * 128 + lane * 4 + 2 * p;
            float* oe = out + (size_t)m0 * 64 + cw * 16;
            float* oo = oe + 64;
            #pragma unroll
            for (int q = 0; q < 4; q++) {
                *(float4*)(oe + 4 * q) = make_float4(dlo[2*q], xhi[2*q], dlo[2*q+1], xhi[2*q+1]);
                *(float4*)(oo + 4 * q) = make_float4(xlo[2*q], dhi[2*q], xlo[2*q+1], dhi[2*q+1]);
            }
        }
    }
}

// ---------------- 5) off-center taps: tiled GEMM + red.v4 scatter -----------
__global__ __launch_bounds__(256, 2) void k_pairs(const float* __restrict__ feats,
                                                  const float* __restrict__ kw,
                                                  float* __restrict__ out) {
    int kk  = blockIdx.x;
    int cnt = g_counts[kk];
    if ((int)(blockIdx.y * BM) >= cnt) return;  // CTA-uniform early exit
    int k   = kk + (kk >= 13);
    int tid = threadIdx.x, wid = tid >> 5, lane = tid & 31;
    int cw = wid >> 1, h = wid & 1;

    extern __shared__ unsigned char sm[];
    ull*   WP = (ull*)(sm + SM_WP);
    float* FS = (float*)(sm + SM_FS);
    int*   JJ = (int*)(sm + SM_JJ);
    int*   II = (int*)(sm + SM_II);

    load_w(WP, kw + k * 4096, tid);

    for (int t = blockIdx.y; t * BM < cnt; t += PMAXT) {
        int tb = t * BM;
        __syncthreads();
        {
            int p = tb + tid;
            if (p < cnt) {
                int2 pr = g_pairs[kk * NPTS + p];
                JJ[tid] = pr.y;
                II[tid] = pr.x;
            } else {
                JJ[tid] = 0;
                II[tid] = -1;
            }
        }
        __syncthreads();
        gather_fs(FS, JJ, feats, tid);
        __syncthreads();

        ull accd[2][8], accx[2][8];
        #pragma unroll
        for (int p = 0; p < 2; p++)
            #pragma unroll
            for (int n = 0; n < 8; n++) { accd[p][n] = 0ULL; accx[p][n] = 0ULL; }

        gemm_core(accd, accx, FS, WP, cw, h, lane);

        #pragma unroll
        for (int p = 0; p < 2; p++) {
            float dlo[8], dhi[8], xlo[8], xhi[8];
            #pragma unroll
            for (int n = 0; n < 8; n++) {
                unpack2(accd[p][n], dlo[n], dhi[n]);
                unpack2(accx[p][n], xlo[n], xhi[n]);
            }
            int ml = h * 128 + lane * 4 + 2 * p;
            int ie = II[ml], io = II[ml + 1];
            if (ie >= 0) {
                float* oe = out + (size_t)ie * 64 + cw * 16;
                #pragma unroll
                for (int q = 0; q < 4; q++)
                    red4(oe + 4 * q, dlo[2*q], xhi[2*q], dlo[2*q+1], xhi[2*q+1]);
            }
            if (io >= 0) {
                float* oo = out + (size_t)io * 64 + cw * 16;
                #pragma unroll
                for (int q = 0; q < 4; q++)
                    red4(oo + 4 * q, xlo[2*q], dhi[2*q], xlo[2*q+1], dhi[2*q+1]);
            }
        }
    }
}

// ---------------- launch -----------------------------------------------------
extern "C" void kernel_launch(void* const* d_in, const int* in_sizes, int n_in,
                              void* d_out, int out_size) {
    const int*   coords = (const int*)d_in[0];
    const float* feats  = (const float*)d_in[1];
    const float* kw     = (const float*)d_in[2];
    float*       out    = (float*)d_out;

    cudaFuncSetAttribute(k_center, cudaFuncAttributeMaxDynamicSharedMemorySize, SM_TOT);
    cudaFuncSetAttribute(k_pairs,  cudaFuncAttributeMaxDynamicSharedMemorySize, SM_TOT);

    k_clear <<<NPTS / 256, 256>>>(coords);
    k_insert<<<NPTS / 256, 256>>>(coords);
    k_probe <<<NPTS / 256, 256>>>(coords);
    k_center<<<CGRID, 256, SM_TOT>>>(coords, feats, kw, out);
    k_pairs <<<dim3(NK, PMAXT), 256, SM_TOT>>>(feats, kw, out);
}

// round 11
// speedup vs baseline: 1.2504x; 1.0640x over previous
#include <cuda_runtime.h>
#include <stdint.h>

#define NPTS   262144
#define GRIDE  256
#define TSIZE  (256*256*256)
#define NK     26
#define BM     128
#define NTILES (NPTS / BM)   // 2048
#define CGRID  296
#define PMAXT  12
#define FSS    132           // FS row stride (floats)

typedef unsigned long long ull;

// ---------------- scratch ---------------------------------------------------
__device__ int  g_table[TSIZE];        // idx+1, 0 = empty
__device__ int  g_counts[NK];
__device__ int  g_cidx[NPTS];          // center-tap gather index per point
__device__ int2 g_pairs[NK * NPTS];

// ---------------- helpers ----------------------------------------------------
__device__ __forceinline__ ull ffma2(ull a, ull b, ull c) {
    ull d;
    asm("fma.rn.f32x2 %0, %1, %2, %3;" : "=l"(d) : "l"(a), "l"(b), "l"(c));
    return d;
}
__device__ __forceinline__ ull pack2(float lo, float hi) {
    ull r;
    asm("mov.b64 %0, {%1, %2};" : "=l"(r) : "f"(lo), "f"(hi));
    return r;
}
__device__ __forceinline__ void unpack2(ull v, float& lo, float& hi) {
    asm("mov.b64 {%0, %1}, %2;" : "=f"(lo), "=f"(hi) : "l"(v));
}
__device__ __forceinline__ ull swap2(ull v) {
    float lo, hi;
    unpack2(v, lo, hi);
    return pack2(hi, lo);
}
__device__ __forceinline__ void red4(float* p, float a, float b, float c, float d) {
    asm volatile("red.global.add.v4.f32 [%0], {%1,%2,%3,%4};"
                 :: "l"(p), "f"(a), "f"(b), "f"(c), "f"(d) : "memory");
}

// ---------------- smem layout (bytes) ---------------------------------------
#define SM_WP   0            // 2048 ull = 16384
#define SM_FS   16384        // 64 * FSS * 4 = 33792
#define SM_JJ   50176        // 2 slots * 128 int
#define SM_II   51200        // 2 slots * 128 int
#define SM_TOT  52224

// ---------------- 1) clear ---------------------------------------------------
__global__ __launch_bounds__(256) void k_clear(const int* __restrict__ coords) {
    int i = blockIdx.x * 256 + threadIdx.x;
    if (blockIdx.x == 0 && threadIdx.x < NK) g_counts[threadIdx.x] = 0;
    int x = coords[3*i], y = coords[3*i+1], z = coords[3*i+2];
    g_table[(x * GRIDE + y) * GRIDE + z] = 0;
}

// ---------------- 2) insert --------------------------------------------------
__global__ __launch_bounds__(256) void k_insert(const int* __restrict__ coords) {
    int i = blockIdx.x * 256 + threadIdx.x;
    int x = coords[3*i], y = coords[3*i+1], z = coords[3*i+2];
    atomicMax(&g_table[(x * GRIDE + y) * GRIDE + z], i + 1);
}

// ---------------- 3) probe (symmetric, 13+1 lookups) -------------------------
__device__ __forceinline__ void wappend(int list, bool valid, int a, int b, int lane) {
    unsigned m = __ballot_sync(0xffffffffu, valid);
    if (!m) return;
    int leader = __ffs(m) - 1;
    int pos = 0;
    if (lane == leader) pos = atomicAdd(&g_counts[list], __popc(m));
    pos = __shfl_sync(0xffffffffu, pos, leader);
    if (valid)
        g_pairs[list * NPTS + pos + __popc(m & ((1u << lane) - 1u))] = make_int2(a, b);
}

__global__ __launch_bounds__(256) void k_probe(const int* __restrict__ coords) {
    int i = blockIdx.x * 256 + threadIdx.x;
    int lane = threadIdx.x & 31;
    int x = coords[3*i], y = coords[3*i+1], z = coords[3*i+2];
    int ti = g_table[(x * GRIDE + y) * GRIDE + z] - 1;
    g_cidx[i] = ti;
    bool winner = (ti == i);

    int jf[13];
    #pragma unroll
    for (int kk = 0; kk < 13; kk++) {
        int nx = x + kk / 9 - 1;
        int ny = y + (kk / 3) % 3 - 1;
        int nz = z + kk % 3 - 1;
        bool inb = ((unsigned)nx < 256u) && ((unsigned)ny < 256u) && ((unsigned)nz < 256u);
        jf[kk] = inb ? g_table[(nx * GRIDE + ny) * GRIDE + nz] : 0;
    }
    #pragma unroll
    for (int kk = 0; kk < 13; kk++) {
        bool v = jf[kk] > 0;
        wappend(kk, v, i, jf[kk] - 1, lane);                 // out[i] tap kk
        wappend(25 - kk, v && winner, jf[kk] - 1, i, lane);  // mirrored: out[j] tap 26-kk
    }
    // rare: duplicate-cell losers self-probe the 13 mirrored taps
    if (__ballot_sync(0xffffffffu, !winner)) {
        #pragma unroll
        for (int kk = 0; kk < 13; kk++) {
            int nx = x - (kk / 9 - 1);
            int ny = y - ((kk / 3) % 3 - 1);
            int nz = z - (kk % 3 - 1);
            bool inb = !winner && ((unsigned)nx < 256u) && ((unsigned)ny < 256u) && ((unsigned)nz < 256u);
            int jr = inb ? g_table[(nx * GRIDE + ny) * GRIDE + nz] : 0;
            wappend(25 - kk, jr > 0, i, jr - 1, lane);
        }
    }
}

// ---------------- GEMM building blocks ---------------------------------------
__device__ __forceinline__ void load_w(ull* WP, const float* __restrict__ Wk, int tid) {
    #pragma unroll 4
    for (int e = tid; e < 2048; e += 256) {
        int ci = e >> 5, p = e & 31;
        float2 w = *(const float2*)(Wk + ci * 64 + 2 * p);
        WP[ci * 32 + p] = pack2(w.x, w.y);
    }
}

__device__ __forceinline__ void ldg_stage(float4 v[8], const int* __restrict__ JJ,
                                          const float* __restrict__ feats, int tid) {
    #pragma unroll
    for (int it = 0; it < 8; it++) {
        int idx = it * 256 + tid;
        int m = idx >> 4, s = idx & 15;
        v[it] = *(const float4*)(feats + (size_t)JJ[m] * 64 + s * 4);
    }
}

__device__ __forceinline__ void sts_stage(float* FS, const float4 v[8], int tid) {
    #pragma unroll
    for (int it = 0; it < 8; it++) {
        int idx = it * 256 + tid;
        int m = idx >> 4, s = idx & 15;
        int pos = m ^ (s * 4);
        float* f = FS + (s * 4) * FSS + pos;
        f[0]       = v[it].x;
        f[FSS]     = v[it].y;
        f[2 * FSS] = v[it].z;
        f[3 * FSS] = v[it].w;
    }
}

// lane tile: 2 m (1 f32x2 pair) x 16 co (8 pairs); diag + antidiag accumulators
__device__ __forceinline__ void gemm128(ull accd[8], ull accx[8], const float* FS,
                                        const ull* WP, int cw, int mbase) {
    const ull* wb = WP + cw * 8;
    #pragma unroll 4
    for (int ci = 0; ci < 64; ci++) {
        ull a = *(const ull*)(FS + ci * FSS + (mbase ^ (ci & 60)));
        ull as = swap2(a);
        const ulonglong2* wq = (const ulonglong2*)(wb + ci * 32);
        ulonglong2 w0 = wq[0], w1 = wq[1], w2 = wq[2], w3 = wq[3];
        ull wp[8] = {w0.x, w0.y, w1.x, w1.y, w2.x, w2.y, w3.x, w3.y};
        #pragma unroll
        for (int n = 0; n < 8; n++) {
            accd[n] = ffma2(a,  wp[n], accd[n]);
            accx[n] = ffma2(as, wp[n], accx[n]);
        }
    }
}

// ---------------- 4) center tap: pipelined persistent GEMM -------------------
__global__ __launch_bounds__(256, 2) void k_center(const float* __restrict__ feats,
                                                   const float* __restrict__ kw,
                                                   float* __restrict__ out) {
    extern __shared__ unsigned char sm[];
    ull*   WP = (ull*)(sm + SM_WP);
    float* FS = (float*)(sm + SM_FS);
    int*   JJ = (int*)(sm + SM_JJ);     // [2][128]

    int tid = threadIdx.x, wid = tid >> 5, lane = tid & 31;
    int cw = wid & 3, h = wid >> 2;
    int mbase = h * 64 + lane * 2;

    load_w(WP, kw + 13 * 4096, tid);

    int t0 = blockIdx.x;
    if (tid < BM) JJ[tid] = g_cidx[t0 * BM + tid];
    __syncthreads();
    float4 v[8];
    ldg_stage(v, JJ, feats, tid);
    int t1 = t0 + CGRID;
    if (t1 < NTILES && tid < BM) JJ[128 + tid] = g_cidx[t1 * BM + tid];
    __syncthreads();
    sts_stage(FS, v, tid);
    __syncthreads();

    int s = 0;
    for (int t = t0; t < NTILES; t += CGRID) {
        int tn = t + CGRID, tn2 = t + 2 * CGRID;
        if (tn < NTILES) ldg_stage(v, JJ + (s ^ 1) * 128, feats, tid);
        int jreg = 0;
        bool hv2 = (tn2 < NTILES) && (tid < BM);
        if (hv2) jreg = g_cidx[tn2 * BM + tid];

        ull accd[8], accx[8];
        #pragma unroll
        for (int n = 0; n < 8; n++) { accd[n] = 0ULL; accx[n] = 0ULL; }
        gemm128(accd, accx, FS, WP, cw, mbase);

        float dlo[8], dhi[8], xlo[8], xhi[8];
        #pragma unroll
        for (int n = 0; n < 8; n++) {
            unpack2(accd[n], dlo[n], dhi[n]);
            unpack2(accx[n], xlo[n], xhi[n]);
        }
        int m0 = t * BM + mbase;
        float* oe = out + (size_t)m0 * 64 + cw * 16;
        float* oo = oe + 64;
        #pragma unroll
        for (int q = 0; q < 4; q++) {
            *(float4*)(oe + 4 * q) = make_float4(dlo[2*q], xhi[2*q], dlo[2*q+1], xhi[2*q+1]);
            *(float4*)(oo + 4 * q) = make_float4(xlo[2*q], dhi[2*q], xlo[2*q+1], dhi[2*q+1]);
        }
        __syncthreads();
        if (tn < NTILES) sts_stage(FS, v, tid);
        if (hv2) JJ[s * 128 + tid] = jreg;
        __syncthreads();
        s ^= 1;
    }
}

// ---------------- 5) off-center taps: pipelined GEMM + red.v4 ----------------
__global__ __launch_bounds__(256, 2) void k_pairs(const float* __restrict__ feats,
                                                  const float* __restrict__ kw,
                                                  float* __restrict__ out) {
    int kk  = blockIdx.x;
    int cnt = g_counts[kk];
    if ((int)(blockIdx.y * BM) >= cnt) return;     // CTA-uniform
    int k   = kk + (kk >= 13);

    extern __shared__ unsigned char sm[];
    ull*   WP = (ull*)(sm + SM_WP);
    float* FS = (float*)(sm + SM_FS);
    int*   JJ = (int*)(sm + SM_JJ);
    int*   II = (int*)(sm + SM_II);

    int tid = threadIdx.x, wid = tid >> 5, lane = tid & 31;
    int cw = wid & 3, h = wid >> 2;
    int mbase = h * 64 + lane * 2;

    load_w(WP, kw + k * 4096, tid);

    int y0 = blockIdx.y;
    if (tid < BM) {
        int p = y0 * BM + tid;
        if (p < cnt) {
            int2 pr = g_pairs[kk * NPTS + p];
            JJ[tid] = pr.y;
            II[tid] = pr.x;
        } else {
            JJ[tid] = 0;
            II[tid] = -1;
        }
    }
    __syncthreads();
    float4 v[8];
    ldg_stage(v, JJ, feats, tid);
    int y1 = y0 + PMAXT;
    if ((y1 * BM) < cnt && tid < BM) {
        int p = y1 * BM + tid;
        if (p < cnt) {
            int2 pr = g_pairs[kk * NPTS + p];
            JJ[128 + tid] = pr.y;
            II[128 + tid] = pr.x;
        } else {
            JJ[128 + tid] = 0;
            II[128 + tid] = -1;
        }
    }
    __syncthreads();
    sts_stage(FS, v, tid);
    __syncthreads();

    int s = 0;
    for (int y = y0; y * BM < cnt; y += PMAXT) {
        int yn = y + PMAXT, yn2 = y + 2 * PMAXT;
        if (yn * BM < cnt) ldg_stage(v, JJ + (s ^ 1) * 128, feats, tid);
        int jreg = 0, ireg = -1;
        bool hv2 = (yn2 * BM < cnt) && (tid < BM);
        if (hv2) {
            int p = yn2 * BM + tid;
            if (p < cnt) {
                int2 pr = g_pairs[kk * NPTS + p];
                jreg = pr.y;
                ireg = pr.x;
            }
        }

        ull accd[8], accx[8];
        #pragma unroll
        for (int n = 0; n < 8; n++) { accd[n] = 0ULL; accx[n] = 0ULL; }
        gemm128(accd, accx, FS, WP, cw, mbase);

        float dlo[8], dhi[8], xlo[8], xhi[8];
        #pragma unroll
        for (int n = 0; n < 8; n++) {
            unpack2(accd[n], dlo[n], dhi[n]);
            unpack2(accx[n], xlo[n], xhi[n]);
        }
        int ie = II[s * 128 + mbase], io = II[s * 128 + mbase + 1];
        if (ie >= 0) {
            float* oe = out + (size_t)ie * 64 + cw * 16;
            #pragma unroll
            for (int q = 0; q < 4; q++)
                red4(oe + 4 * q, dlo[2*q], xhi[2*q], dlo[2*q+1], xhi[2*q+1]);
        }
        if (io >= 0) {
            float* oo = out + (size_t)io * 64 + cw * 16;
            #pragma unroll
            for (int q = 0; q < 4; q++)
                red4(oo + 4 * q, xlo[2*q], dhi[2*q], xlo[2*q+1], dhi[2*q+1]);
        }
        __syncthreads();
        if (yn * BM < cnt) sts_stage(FS, v, tid);
        if (hv2) {
            JJ[s * 128 + tid] = jreg;
            II[s * 128 + tid] = ireg;
        }
        __syncthreads();
        s ^= 1;
    }
}

// ---------------- launch ------------------------------------------------------
extern "C" void kernel_launch(void* const* d_in, const int* in_sizes, int n_in,
                              void* d_out, int out_size) {
    const int*   coords = (const int*)d_in[0];
    const float* feats  = (const float*)d_in[1];
    const float* kw     = (const float*)d_in[2];
    float*       out    = (float*)d_out;

    cudaFuncSetAttribute(k_center, cudaFuncAttributeMaxDynamicSharedMemorySize, SM_TOT);
    cudaFuncSetAttribute(k_pairs,  cudaFuncAttributeMaxDynamicSharedMemorySize, SM_TOT);

    k_clear <<<NPTS / 256, 256>>>(coords);
    k_insert<<<NPTS / 256, 256>>>(coords);
    k_probe <<<NPTS / 256, 256>>>(coords);
    k_center<<<CGRID, 256, SM_TOT>>>(feats, kw, out);
    k_pairs <<<dim3(NK, PMAXT), 256, SM_TOT>>>(feats, kw, out);
}

// round 17
// speedup vs baseline: 1.3231x; 1.0582x over previous
#include <cuda_runtime.h>
#include <stdint.h>

#define NPTS   262144
#define GRIDE  256
#define TSIZE  (256*256*256)
#define NK     26
#define BM     128
#define NTILES (NPTS / BM)   // 2048
#define CGRID  296
#define PY     11
#define PGRID  (NK * PY)     // 286 pairs CTAs
#define FSS    132           // FS row stride (floats)

typedef unsigned long long ull;

// ---------------- scratch ---------------------------------------------------
__device__ int  g_table[TSIZE];        // idx+1, 0 = empty
__device__ int  g_counts[NK];
__device__ int  g_cidx[NPTS];          // center-tap gather index per point
__device__ int2 g_pairs[NK * NPTS];

// ---------------- helpers ----------------------------------------------------
__device__ __forceinline__ ull ffma2(ull a, ull b, ull c) {
    ull d;
    asm("fma.rn.f32x2 %0, %1, %2, %3;" : "=l"(d) : "l"(a), "l"(b), "l"(c));
    return d;
}
__device__ __forceinline__ ull pack2(float lo, float hi) {
    ull r;
    asm("mov.b64 %0, {%1, %2};" : "=l"(r) : "f"(lo), "f"(hi));
    return r;
}
__device__ __forceinline__ void unpack2(ull v, float& lo, float& hi) {
    asm("mov.b64 {%0, %1}, %2;" : "=f"(lo), "=f"(hi) : "l"(v));
}
__device__ __forceinline__ ull swap2(ull v) {
    float lo, hi;
    unpack2(v, lo, hi);
    return pack2(hi, lo);
}
__device__ __forceinline__ void red4(float* p, float a, float b, float c, float d) {
    asm volatile("red.global.add.v4.f32 [%0], {%1,%2,%3,%4};"
                 :: "l"(p), "f"(a), "f"(b), "f"(c), "f"(d) : "memory");
}

// ---------------- smem layout (bytes) ---------------------------------------
#define SM_WP   0            // 2048 ull = 16384
#define SM_FS   16384        // 64 * FSS * 4 = 33792
#define SM_JJ   50176        // 2 slots * 128 int
#define SM_II   51200        // 2 slots * 128 int
#define SM_TOT  52224

// ---------------- 1) clear ---------------------------------------------------
__global__ __launch_bounds__(256) void k_clear(const int* __restrict__ coords) {
    int i = blockIdx.x * 256 + threadIdx.x;
    if (blockIdx.x == 0 && threadIdx.x < NK) g_counts[threadIdx.x] = 0;
    int x = coords[3*i], y = coords[3*i+1], z = coords[3*i+2];
    g_table[(x * GRIDE + y) * GRIDE + z] = 0;
}

// ---------------- 2) insert --------------------------------------------------
__global__ __launch_bounds__(256) void k_insert(const int* __restrict__ coords) {
    int i = blockIdx.x * 256 + threadIdx.x;
    int x = coords[3*i], y = coords[3*i+1], z = coords[3*i+2];
    atomicMax(&g_table[(x * GRIDE + y) * GRIDE + z], i + 1);
}

// ---------------- 3) probe (symmetric, 13+1 lookups) -------------------------
__device__ __forceinline__ void wappend(int list, bool valid, int a, int b, int lane) {
    unsigned m = __ballot_sync(0xffffffffu, valid);
    if (!m) return;
    int leader = __ffs(m) - 1;
    int pos = 0;
    if (lane == leader) pos = atomicAdd(&g_counts[list], __popc(m));
    pos = __shfl_sync(0xffffffffu, pos, leader);
    if (valid)
        g_pairs[list * NPTS + pos + __popc(m & ((1u << lane) - 1u))] = make_int2(a, b);
}

__global__ __launch_bounds__(256) void k_probe(const int* __restrict__ coords) {
    int i = blockIdx.x * 256 + threadIdx.x;
    int lane = threadIdx.x & 31;
    int x = coords[3*i], y = coords[3*i+1], z = coords[3*i+2];
    int ti = g_table[(x * GRIDE + y) * GRIDE + z] - 1;
    g_cidx[i] = ti;
    bool winner = (ti == i);

    int jf[13];
    #pragma unroll
    for (int kk = 0; kk < 13; kk++) {
        int nx = x + kk / 9 - 1;
        int ny = y + (kk / 3) % 3 - 1;
        int nz = z + kk % 3 - 1;
        bool inb = ((unsigned)nx < 256u) && ((unsigned)ny < 256u) && ((unsigned)nz < 256u);
        jf[kk] = inb ? g_table[(nx * GRIDE + ny) * GRIDE + nz] : 0;
    }
    #pragma unroll
    for (int kk = 0; kk < 13; kk++) {
        bool v = jf[kk] > 0;
        wappend(kk, v, i, jf[kk] - 1, lane);                 // out[i] tap kk
        wappend(25 - kk, v && winner, jf[kk] - 1, i, lane);  // mirrored: out[j] tap 26-kk
    }
    // rare: duplicate-cell losers self-probe the 13 mirrored taps
    if (__ballot_sync(0xffffffffu, !winner)) {
        #pragma unroll
        for (int kk = 0; kk < 13; kk++) {
            int nx = x - (kk / 9 - 1);
            int ny = y - ((kk / 3) % 3 - 1);
            int nz = z - (kk % 3 - 1);
            bool inb = !winner && ((unsigned)nx < 256u) && ((unsigned)ny < 256u) && ((unsigned)nz < 256u);
            int jr = inb ? g_table[(nx * GRIDE + ny) * GRIDE + nz] : 0;
            wappend(25 - kk, jr > 0, i, jr - 1, lane);
        }
    }
}

// ---------------- GEMM building blocks ---------------------------------------
__device__ __forceinline__ void load_w(ull* WP, const float* __restrict__ Wk, int tid) {
    #pragma unroll 4
    for (int e = tid; e < 2048; e += 256) {
        int ci = e >> 5, p = e & 31;
        float2 w = *(const float2*)(Wk + ci * 64 + 2 * p);
        WP[ci * 32 + p] = pack2(w.x, w.y);
    }
}

__device__ __forceinline__ void ldg_stage(float4 v[8], const int* __restrict__ JJ,
                                          const float* __restrict__ feats, int tid) {
    #pragma unroll
    for (int it = 0; it < 8; it++) {
        int idx = it * 256 + tid;
        int m = idx >> 4, s = idx & 15;
        v[it] = *(const float4*)(feats + (size_t)JJ[m] * 64 + s * 4);
    }
}

__device__ __forceinline__ void sts_stage(float* FS, const float4 v[8], int tid) {
    #pragma unroll
    for (int it = 0; it < 8; it++) {
        int idx = it * 256 + tid;
        int m = idx >> 4, s = idx & 15;
        int pos = m ^ (s * 4);
        float* f = FS + (s * 4) * FSS + pos;
        f[0]       = v[it].x;
        f[FSS]     = v[it].y;
        f[2 * FSS] = v[it].z;
        f[3 * FSS] = v[it].w;
    }
}

// lane tile: 2 m (1 f32x2 pair) x 16 co (8 pairs); diag + antidiag accumulators
// XOR swizzle hoisted: invariant per 4-ci group.
__device__ __forceinline__ void gemm128(ull accd[8], ull accx[8], const float* FS,
                                        const ull* WP, int cw, int mbase) {
    const ull* wb = WP + cw * 8;
    #pragma unroll 2
    for (int g = 0; g < 16; g++) {
        const float* fg = FS + (mbase ^ (g * 4)) + (g * 4) * FSS;
        const ull*   wg = wb + (g * 4) * 32;
        #pragma unroll
        for (int j = 0; j < 4; j++) {
            ull a = *(const ull*)(fg + j * FSS);
            ull as = swap2(a);
            const ulonglong2* wq = (const ulonglong2*)(wg + j * 32);
            ulonglong2 w0 = wq[0], w1 = wq[1], w2 = wq[2], w3 = wq[3];
            ull wp[8] = {w0.x, w0.y, w1.x, w1.y, w2.x, w2.y, w3.x, w3.y};
            #pragma unroll
            for (int n = 0; n < 8; n++) {
                accd[n] = ffma2(a,  wp[n], accd[n]);
                accx[n] = ffma2(as, wp[n], accx[n]);
            }
        }
    }
}

// ---------------- 4) fused GEMM: pairs CTAs first, then center CTAs ----------
__global__ __launch_bounds__(256, 2) void k_gemm(const float* __restrict__ feats,
                                                 const float* __restrict__ kw,
                                                 float* __restrict__ out) {
    extern __shared__ unsigned char sm[];
    ull*   WP = (ull*)(sm + SM_WP);
    float* FS = (float*)(sm + SM_FS);
    int*   JJ = (int*)(sm + SM_JJ);     // [2][128]
    int*   II = (int*)(sm + SM_II);     // [2][128]

    int tid = threadIdx.x, wid = tid >> 5, lane = tid & 31;
    int cw = wid & 3, h = wid >> 2;
    int mbase = h * 64 + lane * 2;
    int bx = blockIdx.x;

    if (bx >= PGRID) {
        // ================= CENTER path (persistent, pipelined) ===============
        int t0 = bx - PGRID;
        load_w(WP, kw + 13 * 4096, tid);

        if (tid < BM) JJ[tid] = g_cidx[t0 * BM + tid];
        __syncthreads();
        float4 v[8];
        ldg_stage(v, JJ, feats, tid);
        int t1 = t0 + CGRID;
        if (t1 < NTILES && tid < BM) JJ[128 + tid] = g_cidx[t1 * BM + tid];
        __syncthreads();
        sts_stage(FS, v, tid);
        __syncthreads();

        int s = 0;
        for (int t = t0; t < NTILES; t += CGRID) {
            int tn = t + CGRID, tn2 = t + 2 * CGRID;
            if (tn < NTILES) ldg_stage(v, JJ + (s ^ 1) * 128, feats, tid);
            int jreg = 0;
            bool hv2 = (tn2 < NTILES) && (tid < BM);
            if (hv2) jreg = g_cidx[tn2 * BM + tid];

            ull accd[8], accx[8];
            #pragma unroll
            for (int n = 0; n < 8; n++) { accd[n] = 0ULL; accx[n] = 0ULL; }
            gemm128(accd, accx, FS, WP, cw, mbase);

            float dlo[8], dhi[8], xlo[8], xhi[8];
            #pragma unroll
            for (int n = 0; n < 8; n++) {
                unpack2(accd[n], dlo[n], dhi[n]);
                unpack2(accx[n], xlo[n], xhi[n]);
            }
            int m0 = t * BM + mbase;
            float* oe = out + (size_t)m0 * 64 + cw * 16;
            float* oo = oe + 64;
            #pragma unroll
            for (int q = 0; q < 4; q++) {
                red4(oe + 4 * q, dlo[2*q], xhi[2*q], dlo[2*q+1], xhi[2*q+1]);
                red4(oo + 4 * q, xlo[2*q], dhi[2*q], xlo[2*q+1], dhi[2*q+1]);
            }
            __syncthreads();
            if (tn < NTILES) sts_stage(FS, v, tid);
            if (hv2) JJ[s * 128 + tid] = jreg;
            __syncthreads();
            s ^= 1;
        }
    } else {
        // ================= PAIRS path (per-tap, pipelined) ===================
        int kk  = bx / PY;
        int y0  = bx % PY;
        int cnt = g_counts[kk];
        if (y0 * BM >= cnt) return;                // CTA-uniform
        int k = kk + (kk >= 13);

        load_w(WP, kw + k * 4096, tid);

        if (tid < BM) {
            int p = y0 * BM + tid;
            if (p < cnt) {
                int2 pr = g_pairs[kk * NPTS + p];
                JJ[tid] = pr.y;
                II[tid] = pr.x;
            } else {
                JJ[tid] = 0;
                II[tid] = -1;
            }
        }
        __syncthreads();
        float4 v[8];
        ldg_stage(v, JJ, feats, tid);
        int y1 = y0 + PY;
        if ((y1 * BM) < cnt && tid < BM) {
            int p = y1 * BM + tid;
            if (p < cnt) {
                int2 pr = g_pairs[kk * NPTS + p];
                JJ[128 + tid] = pr.y;
                II[128 + tid] = pr.x;
            } else {
                JJ[128 + tid] = 0;
                II[128 + tid] = -1;
            }
        }
        __syncthreads();
        sts_stage(FS, v, tid);
        __syncthreads();

        int s = 0;
        for (int y = y0; y * BM < cnt; y += PY) {
            int yn = y + PY, yn2 = y + 2 * PY;
            if (yn * BM < cnt) ldg_stage(v, JJ + (s ^ 1) * 128, feats, tid);
            int jreg = 0, ireg = -1;
            bool hv2 = (yn2 * BM < cnt) && (tid < BM);
            if (hv2) {
                int p = yn2 * BM + tid;
                if (p < cnt) {
                    int2 pr = g_pairs[kk * NPTS + p];
                    jreg = pr.y;
                    ireg = pr.x;
                }
            }

            ull accd[8], accx[8];
            #pragma unroll
            for (int n = 0; n < 8; n++) { accd[n] = 0ULL; accx[n] = 0ULL; }
            gemm128(accd, accx, FS, WP, cw, mbase);

            float dlo[8], dhi[8], xlo[8], xhi[8];
            #pragma unroll
            for (int n = 0; n < 8; n++) {
                unpack2(accd[n], dlo[n], dhi[n]);
                unpack2(accx[n], xlo[n], xhi[n]);
            }
            int ie = II[s * 128 + mbase], io = II[s * 128 + mbase + 1];
            if (ie >= 0) {
                float* oe = out + (size_t)ie * 64 + cw * 16;
                #pragma unroll
                for (int q = 0; q < 4; q++)
                    red4(oe + 4 * q, dlo[2*q], xhi[2*q], dlo[2*q+1], xhi[2*q+1]);
            }
            if (io >= 0) {
                float* oo = out + (size_t)io * 64 + cw * 16;
                #pragma unroll
                for (int q = 0; q < 4; q++)
                    red4(oo + 4 * q, xlo[2*q], dhi[2*q], xlo[2*q+1], dhi[2*q+1]);
            }
            __syncthreads();
            if (yn * BM < cnt) sts_stage(FS, v, tid);
            if (hv2) {
                JJ[s * 128 + tid] = jreg;
                II[s * 128 + tid] = ireg;
            }
            __syncthreads();
            s ^= 1;
        }
    }
}

// ---------------- launch ------------------------------------------------------
extern "C" void kernel_launch(void* const* d_in, const int* in_sizes, int n_in,
                              void* d_out, int out_size) {
    const int*   coords = (const int*)d_in[0];
    const float* feats  = (const float*)d_in[1];
    const float* kw     = (const float*)d_in[2];
    float*       out    = (float*)d_out;

    cudaFuncSetAttribute(k_gemm, cudaFuncAttributeMaxDynamicSharedMemorySize, SM_TOT);

    cudaMemsetAsync(out, 0, (size_t)out_size * sizeof(float));
    k_clear <<<NPTS / 256, 256>>>(coords);
    k_insert<<<NPTS / 256, 256>>>(coords);
    k_probe <<<NPTS / 256, 256>>>(coords);
    k_gemm  <<<PGRID + CGRID, 256, SM_TOT>>>(feats, kw, out);
}